// round 4
// baseline (speedup 1.0000x reference)
#include <cuda_runtime.h>
#include <cstdint>
#include <cstddef>

#define Bdim 64
#define Tdim 1024
#define Fdim 512

#define NBLK 128
#define JT 8
#define BT 32
#define PAD 516   // 516 % 32 == 4 -> conflict-free row offsets for 8 j-lanes / 4 b-lanes

// Scratch (device globals: allocation-free per harness rules)
__device__ float    g_G[(size_t)Bdim * Tdim * 2 * Fdim];  // [B*T][1024]: cols 0..511 = hid logit, 512..1023 = w logit (x-part + bias)
__device__ float    g_h[2][Bdim * Fdim];                  // double-buffered hidden state
__device__ unsigned g_cnt;                                // grid barrier counter (monotonic within a launch)
__device__ int      g_done_mode;                          // 0 = uint8, 1 = int32, 2 = float32

// ---- packed fp32x2 helpers (sm_100+ PTX) ----
__device__ __forceinline__ void fma2(unsigned long long& acc, unsigned long long a, unsigned long long b) {
    asm("fma.rn.f32x2 %0, %1, %2, %0;" : "+l"(acc) : "l"(a), "l"(b));
}
__device__ __forceinline__ unsigned long long pack2(float x, float y) {
    unsigned long long r;
    asm("mov.b64 %0, {%1, %2};" : "=l"(r) : "f"(x), "f"(y));
    return r;
}
__device__ __forceinline__ void unpack2(unsigned long long v, float& x, float& y) {
    asm("mov.b64 {%0, %1}, %2;" : "=f"(x), "=f"(y) : "l"(v));
}

// ============================================================================
// Kernel A: time-parallel pre-GEMM.
//   G[m][j]       = sum_k X[m][k] * Wh[k][j] + bh[j]     (j in 0..511)
//   G[m][512 + j] = sum_k X[m][k] * Ww[k][j] + bw[j]
// M = B*T = 65536, N = 1024 (16 tiles of 64: 8 per weight matrix), K = 512.
// Block tile 128x64x16, 256 threads, per-thread 8x4 micro-tile with f32x2 FMAs.
// Block (0,0) additionally: inits g_h[0], resets g_cnt, detects done dtype.
// ============================================================================
__global__ void __launch_bounds__(256) gemm_pre(
    const float* __restrict__ X, const float* __restrict__ Wh, const float* __restrict__ Ww,
    const float* __restrict__ bh, const float* __restrict__ bw, const float* __restrict__ hidden,
    const void* __restrict__ done_raw)
{
    __shared__ float As[16][132];   // A tile transposed [k][m], padded
    __shared__ float Bs[16 * 64];   // B tile [k][n]

    const int tid = threadIdx.x;

    if (blockIdx.x == 0 && blockIdx.y == 0) {
        for (int i = tid; i < Bdim * Fdim; i += 256) g_h[0][i] = hidden[i];
        if (tid == 0) {
            g_cnt = 0u;
            // Detect the dtype the harness used for the bool `done` tensor.
            // First 1024 bytes exist under every interpretation (min 65536 B).
            const unsigned* pi = (const unsigned*)done_raw;
            bool i32ok = true, f32ok = true;
            for (int i = 0; i < 256; i++) {
                unsigned v = pi[i];
                if (v > 1u) i32ok = false;
                if (v != 0u && v != 0x3F800000u) f32ok = false;
            }
            g_done_mode = i32ok ? 1 : (f32ok ? 2 : 0);
        }
    }

    const int mBase = blockIdx.y * 128;
    const int nTile = blockIdx.x;                 // 0..15
    const bool isW  = nTile >= 8;
    const float* __restrict__ W    = isW ? Ww : Wh;
    const float* __restrict__ bias = isW ? bw : bh;
    const int col0 = (nTile & 7) * 64;

    const int ty = tid >> 4, tx = tid & 15;
    const int m0 = ty * 8, n0 = tx * 4;

    unsigned long long acc[4][4];                 // [m-pair][n], pairs along m
#pragma unroll
    for (int i = 0; i < 4; i++)
#pragma unroll
        for (int j = 0; j < 4; j++) acc[i][j] = 0ull;

    for (int ko = 0; ko < Fdim; ko += 16) {
        // Load A tile (128 rows x 16 k), transpose into smem
#pragma unroll
        for (int i = 0; i < 2; i++) {
            int v   = tid * 2 + i;                // 0..511 float4 slots
            int row = v >> 2, kq = v & 3;
            float4 a = *(const float4*)&X[(size_t)(mBase + row) * Fdim + ko + kq * 4];
            As[kq * 4 + 0][row] = a.x;
            As[kq * 4 + 1][row] = a.y;
            As[kq * 4 + 2][row] = a.z;
            As[kq * 4 + 3][row] = a.w;
        }
        // Load B tile (16 k x 64 n)
        {
            int kr = tid >> 4, cq = tid & 15;
            *(float4*)&Bs[kr * 64 + cq * 4] =
                *(const float4*)&W[(size_t)(ko + kr) * Fdim + col0 + cq * 4];
        }
        __syncthreads();

#pragma unroll
        for (int kk = 0; kk < 16; kk++) {
            ulonglong2 a01 = *(const ulonglong2*)&As[kk][m0];       // (m0,m0+1),(m0+2,m0+3)
            ulonglong2 a23 = *(const ulonglong2*)&As[kk][m0 + 4];
            float4 b = *(const float4*)&Bs[kk * 64 + n0];
            unsigned long long bb0 = pack2(b.x, b.x);
            unsigned long long bb1 = pack2(b.y, b.y);
            unsigned long long bb2 = pack2(b.z, b.z);
            unsigned long long bb3 = pack2(b.w, b.w);
            unsigned long long aa[4] = { a01.x, a01.y, a23.x, a23.y };
#pragma unroll
            for (int mp = 0; mp < 4; mp++) {
                fma2(acc[mp][0], aa[mp], bb0);
                fma2(acc[mp][1], aa[mp], bb1);
                fma2(acc[mp][2], aa[mp], bb2);
                fma2(acc[mp][3], aa[mp], bb3);
            }
        }
        __syncthreads();
    }

    // Epilogue: add bias, write G
    float4 bv = *(const float4*)&bias[col0 + n0];
    const int gcol = (isW ? Fdim : 0) + col0 + n0;
#pragma unroll
    for (int mp = 0; mp < 4; mp++) {
        float c0x, c0y, c1x, c1y, c2x, c2y, c3x, c3y;
        unpack2(acc[mp][0], c0x, c0y);
        unpack2(acc[mp][1], c1x, c1y);
        unpack2(acc[mp][2], c2x, c2y);
        unpack2(acc[mp][3], c3x, c3y);
        float4 r0 = make_float4(c0x + bv.x, c1x + bv.y, c2x + bv.z, c3x + bv.w);
        float4 r1 = make_float4(c0y + bv.x, c1y + bv.y, c2y + bv.z, c3y + bv.w);
        size_t row0 = (size_t)(mBase + m0 + 2 * mp) * (2 * Fdim) + gcol;
        *(float4*)&g_G[row0]            = r0;
        *(float4*)&g_G[row0 + 2 * Fdim] = r1;
    }
}

// ============================================================================
// Kernel B: recurrence. 128 persistent blocks (99KB smem -> 2/SM capacity,
// all co-resident on 148 SMs), one software grid barrier per step,
// double-buffered h in L2. Block (jt, bt): 8 output features x 32 batch rows.
// Recurrent weight columns live in smem for all 1024 steps; h tile reloaded
// from g_h each step. Thread (bl, jl): A_h, A_w dots over k=512 via f32x2.
// G / X / done operands for the step are PREFETCHED before the dot loop so
// their DRAM/L2 latency hides under ~3000 cyc of LDS+FMA work.
// ============================================================================
__global__ void __launch_bounds__(256) rnn_rec(
    const float* __restrict__ X, const void* __restrict__ done_raw,
    const float* __restrict__ Wh, const float* __restrict__ Ww, float* __restrict__ out,
    int write_hfinal)
{
    extern __shared__ float sm[];
    float* swh = sm;                  // [JT][PAD]
    float* sww = sm + JT * PAD;       // [JT][PAD]
    float* shh = sm + 2 * JT * PAD;   // [BT][PAD]

    const int tid = threadIdx.x;
    const int jt = blockIdx.x & 63;
    const int bt = blockIdx.x >> 6;
    const int j0 = jt * JT, b0 = bt * BT;

    const int dmode = g_done_mode;    // written by gemm_pre (stream-ordered)
    const unsigned char* d8  = (const unsigned char*)done_raw;
    const int*           d32 = (const int*)done_raw;
    const float*         df  = (const float*)done_raw;

    // One-time: recurrent weight columns -> smem (resident for all 1024 steps)
    for (int v = tid; v < JT * Fdim; v += 256) {
        int k = v >> 3, jl = v & 7;
        swh[jl * PAD + k] = Wh[(size_t)(Fdim + k) * Fdim + j0 + jl];
        sww[jl * PAD + k] = Ww[(size_t)(Fdim + k) * Fdim + j0 + jl];
    }

    const int jl = tid & 7, bl = tid >> 3;
    const int j = j0 + jl, b = b0 + bl;
    const float* ph  = &shh[bl * PAD];
    const float* pwh = &swh[jl * PAD];
    const float* pww = &sww[jl * PAD];

    unsigned tgt = 0;
    for (int t = 0; t < Tdim; t++) {
        const int cur = t & 1;

        // ---- Prefetch this step's global operands (independent of the dots;
        //      issued first so DRAM/L2 latency overlaps the LDS/FMA loop). ----
        const size_t m   = (size_t)b * Tdim + t;
        const float gh_v = g_G[m * (2 * Fdim) + j];
        const float gw_v = g_G[m * (2 * Fdim) + Fdim + j];
        const float x    = X[m * Fdim + j];
        bool dflag;
        if (dmode == 1)      dflag = (d32[m] != 0);
        else if (dmode == 2) dflag = (df[m]  != 0.0f);
        else                 dflag = (d8[m]  != 0);

        // Load h tile [BT x 512] from global double buffer (coalesced float4)
        for (int v = tid; v < BT * (Fdim / 4); v += 256) {
            int blb = v >> 7, kq = v & 127;
            *(float4*)&shh[blb * PAD + kq * 4] =
                *(const float4*)&g_h[cur][(b0 + blb) * Fdim + kq * 4];
        }
        __syncthreads();   // weights (first iter) + h tile ready

        unsigned long long ah0 = 0, ah1 = 0, aw0 = 0, aw1 = 0;
#pragma unroll 8
        for (int k = 0; k < Fdim; k += 4) {
            ulonglong2 hv = *(const ulonglong2*)&ph[k];
            ulonglong2 wh = *(const ulonglong2*)&pwh[k];
            ulonglong2 ww = *(const ulonglong2*)&pww[k];
            fma2(ah0, hv.x, wh.x);
            fma2(ah1, hv.y, wh.y);
            fma2(aw0, hv.x, ww.x);
            fma2(aw1, hv.y, ww.y);
        }
        float e0, e1, e2, e3;
        unpack2(ah0, e0, e1); unpack2(ah1, e2, e3);
        const float dot_h = (e0 + e2) + (e1 + e3);
        unpack2(aw0, e0, e1); unpack2(aw1, e2, e3);
        const float dot_w = (e0 + e2) + (e1 + e3);

        const float ahv = gh_v + dot_h;
        const float awv = gw_v + dot_w;
        const float hid = tanhf(ahv);
        const float w   = 1.0f / (1.0f + __expf(-awv));
        const float o   = hid + w * (x - hid);            // w*x + (1-w)*hid
        out[m * Fdim + j] = o;

        const float hn = dflag ? 0.0f : o;
        g_h[cur ^ 1][b * Fdim + j] = hn;
        if (write_hfinal && t == Tdim - 1)
            out[(size_t)Bdim * Tdim * Fdim + b * Fdim + j] = hn;

        // Grid barrier (monotonic counter; reset by gemm_pre next launch)
        tgt += NBLK;
        if (t < Tdim - 1) {
            __syncthreads();                  // all smem reads/writes done in-block
            if (tid == 0) {
                __threadfence();              // release: make h/out writes visible
                atomicAdd(&g_cnt, 1u);
                while (*((volatile unsigned*)&g_cnt) < tgt) { }
            }
            __syncthreads();
            __threadfence();                  // acquire before reading g_h next iter
        }
    }
}

extern "C" void kernel_launch(void* const* d_in, const int* in_sizes, int n_in,
                              void* d_out, int out_size)
{
    const float* input  = (const float*)d_in[0];
    const float* hidden = (const float*)d_in[1];
    const void*  done   = d_in[2];
    const float* Wh     = (const float*)d_in[3];
    const float* bh     = (const float*)d_in[4];
    const float* Ww     = (const float*)d_in[5];
    const float* bw     = (const float*)d_in[6];
    float*       out    = (float*)d_out;

    const int write_hfinal = (out_size >= Bdim * Tdim * Fdim + Bdim * Fdim) ? 1 : 0;

    const int smem_bytes = (2 * JT + BT) * PAD * sizeof(float);  // 99072 B
    cudaFuncSetAttribute(rnn_rec, cudaFuncAttributeMaxDynamicSharedMemorySize, smem_bytes);

    gemm_pre<<<dim3(16, 512), 256>>>(input, Wh, Ww, bh, bw, hidden, done);
    rnn_rec<<<NBLK, 256, smem_bytes>>>(input, done, Wh, Ww, out, write_hfinal);
}